// round 11
// baseline (speedup 1.0000x reference)
#include <cuda_runtime.h>
#include <cstdint>

// ---------------- problem constants ----------------
#define Hh  64
#define Ww  64
#define Cc  64
#define Uu  64
#define OHh 30
#define OWw 30
#define KDIM   1600           // 5*5*64
#define NCHUNK 50             // K32 chunks
#define LDSS   36             // B smem row stride (banks 4g+t+kb all-distinct)
#define NSTG   3
#define XBSTR  (Hh * Ww * Cc) // x batch stride in floats (262144)

// Raw fp32 bits into the tf32 mma (truncation-to-tf32).
__device__ __forceinline__ uint32_t tf32_bits(float v) { return __float_as_uint(v); }

__device__ __forceinline__ void mma_16n8k8(float c[4], const uint32_t a[4], const uint32_t b[2]) {
    asm volatile(
        "mma.sync.aligned.m16n8k8.row.col.f32.tf32.tf32.f32 "
        "{%0,%1,%2,%3}, {%4,%5,%6,%7}, {%8,%9}, {%0,%1,%2,%3};"
        : "+f"(c[0]), "+f"(c[1]), "+f"(c[2]), "+f"(c[3])
        : "r"(a[0]), "r"(a[1]), "r"(a[2]), "r"(a[3]), "r"(b[0]), "r"(b[1]));
}

__device__ __forceinline__ void cp16_ef(uint32_t dst, const float* src, uint64_t pol) {
    asm volatile("cp.async.cg.shared.global.L2::cache_hint [%0], [%1], 16, %2;"
                 :: "r"(dst), "l"(src), "l"(pol));
}
#define CP_COMMIT() asm volatile("cp.async.commit_group;" ::: "memory")

// ---------------- kernel ----------------
// Warp wid computes batches [wid*16, wid*16+16) x all 64 units.
// A (x) fragments: direct LDG from global (x is L2-resident; W streams evict_first).
// B (w) tile: cp.async 3-stage smem ring, one barrier per chunk.
__global__ void __launch_bounds__(128, 6)
freeconv_mma_kernel(const float* __restrict__ x, const float* __restrict__ w,
                    const float* __restrict__ bias, float* __restrict__ out) {
    __shared__ float Bs[NSTG][64][LDSS];
    __shared__ float bsh[64];

    const int tid  = threadIdx.x;
    const int wid  = tid >> 5;
    const int lane = tid & 31;
    const int g    = lane >> 2;     // 0..7
    const int t    = lane & 3;      // 0..3
    const int tile = blockIdx.x;
    const int oh = tile / OWw, ow = tile % OWw;
    const int ih0 = oh * 2, iw0 = ow * 2;

    uint64_t pol;
    asm("createpolicy.fractional.L2::evict_first.b64 %0, 1.0;" : "=l"(pol));

    if (tid < 64) bsh[tid] = bias[(size_t)tile * Uu + tid];

    const size_t wtile = (size_t)tile * Uu * KDIM;

    // x row pointers for this thread's two batch rows (m = wid*16+g, +8)
    const float* xr0 = x + (size_t)(wid * 16 + g) * XBSTR;
    const float* xr1 = xr0 + (size_t)8 * XBSTR;

    // Stage one K=32 B-chunk: 64 unit-rows x 128B.
    auto load_B = [&](int c, int s) {
        const int ij = c >> 1, ch = c & 1;
        const int i = ij / 5, j = ij - i * 5;
        const float* wsrc = w + wtile + (size_t)c * 32;
        (void)i; (void)j; (void)ch;
#pragma unroll
        for (int it = 0; it < 4; it++) {
            const int idx = tid + it * 128;      // 0..511
            const int row = idx >> 3, c16 = idx & 7;
            uint32_t bd = (uint32_t)__cvta_generic_to_shared(&Bs[s][row][0]) + c16 * 16;
            cp16_ef(bd, wsrc + (size_t)row * KDIM + c16 * 4, pol);
        }
    };

    float acc[8][4];
#pragma unroll
    for (int nt = 0; nt < 8; nt++)
#pragma unroll
        for (int r = 0; r < 4; r++) acc[nt][r] = 0.0f;

    // prologue: B chunks 0,1 in flight
    load_B(0, 0); CP_COMMIT();
    load_B(1, 1); CP_COMMIT();

    for (int c = 0; c < NCHUNK; c++) {
        const int s = c % NSTG;
        if (c + 2 < NCHUNK) {
            asm volatile("cp.async.wait_group 1;" ::: "memory");   // chunk c resident
        } else {
            asm volatile("cp.async.wait_group 0;" ::: "memory");
        }
        __syncthreads();   // B(c) visible; stage (c+2)%3 consumed at iter c-1

        if (c + 2 < NCHUNK) {
            load_B(c + 2, (c + 2) % NSTG);
            CP_COMMIT();
        }

        // x word offset for chunk c: (i, j, ch)
        const int ij = c >> 1, ch = c & 1;
        const int i = ij / 5, j = ij - i * 5;
        const size_t xoff = (((size_t)(ih0 + i) * Ww) + (iw0 + j)) * Cc + ch * 32;
        const float* xa0 = xr0 + xoff;   // this thread's batch row (m = wid*16+g)
        const float* xa1 = xr1 + xoff;   // m + 8

#pragma unroll
        for (int k8 = 0; k8 < 4; k8++) {
            const int kb = k8 * 8;
            uint32_t a[4];
            a[0] = tf32_bits(xa0[kb + t]);
            a[1] = tf32_bits(xa1[kb + t]);
            a[2] = tf32_bits(xa0[kb + t + 4]);
            a[3] = tf32_bits(xa1[kb + t + 4]);
#pragma unroll
            for (int nt = 0; nt < 8; nt++) {
                const int n0 = nt * 8 + g;
                uint32_t b[2];
                b[0] = tf32_bits(Bs[s][n0][kb + t]);
                b[1] = tf32_bits(Bs[s][n0][kb + t + 4]);
                mma_16n8k8(acc[nt], a, b);
            }
        }
    }

    // epilogue: rows m = wid*16+g (+8), cols u = nt*8 + 2t
    const int r0 = wid * 16 + g;
#pragma unroll
    for (int nt = 0; nt < 8; nt++) {
        const int col = nt * 8 + 2 * t;
        const float b0 = bsh[col], b1 = bsh[col + 1];
        float* op0 = out + (((size_t)r0 * OHh + oh) * OWw + ow) * Uu + col;
        float* op1 = out + (((size_t)(r0 + 8) * OHh + oh) * OWw + ow) * Uu + col;
        float2 v0 = make_float2(acc[nt][0] + b0, acc[nt][1] + b1);
        float2 v1 = make_float2(acc[nt][2] + b0, acc[nt][3] + b1);
        *reinterpret_cast<float2*>(op0) = v0;
        *reinterpret_cast<float2*>(op1) = v1;
    }
}

// ---------------- launch ----------------
extern "C" void kernel_launch(void* const* d_in, const int* in_sizes, int n_in,
                              void* d_out, int out_size) {
    (void)in_sizes; (void)n_in; (void)out_size;
    const float* x = (const float*)d_in[0];
    const float* w = (const float*)d_in[1];
    const float* b = (const float*)d_in[2];
    freeconv_mma_kernel<<<OHh * OWw, 128>>>(x, w, b, (float*)d_out);
}

// round 12
// speedup vs baseline: 1.2545x; 1.2545x over previous
#include <cuda_runtime.h>
#include <cstdint>

// ---------------- problem constants ----------------
#define Hh  64
#define Ww  64
#define Cc  64
#define Uu  64
#define OHh 30
#define OWw 30
#define KDIM   1600           // 5*5*64
#define NCHUNK 50             // K32 chunks
#define LDSS   36             // smem row stride in floats (bank=(4g+t)%32 -> conflict-free)

// Raw fp32 bits into the tf32 mma (truncation-to-tf32): no cvt in mainloop.
__device__ __forceinline__ uint32_t tf32_bits(float v) { return __float_as_uint(v); }

__device__ __forceinline__ void mma_16n8k8(float c[4], const uint32_t a[4], const uint32_t b[2]) {
    asm volatile(
        "mma.sync.aligned.m16n8k8.row.col.f32.tf32.tf32.f32 "
        "{%0,%1,%2,%3}, {%4,%5,%6,%7}, {%8,%9}, {%0,%1,%2,%3};"
        : "+f"(c[0]), "+f"(c[1]), "+f"(c[2]), "+f"(c[3])
        : "r"(a[0]), "r"(a[1]), "r"(a[2]), "r"(a[3]), "r"(b[0]), "r"(b[1]));
}

__device__ __forceinline__ void cp16(uint32_t dst, const float* src) {
    asm volatile("cp.async.cg.shared.global [%0], [%1], 16;" :: "r"(dst), "l"(src));
}
// W is streaming / read-once: evict_first so it doesn't blow x out of L2.
__device__ __forceinline__ void cp16_ef(uint32_t dst, const float* src, uint64_t pol) {
    asm volatile("cp.async.cg.shared.global.L2::cache_hint [%0], [%1], 16, %2;"
                 :: "r"(dst), "l"(src), "l"(pol));
}
#define CP_COMMIT() asm volatile("cp.async.commit_group;" ::: "memory")

// ---------------- kernel ----------------
// Split-N: CTA = (tile, half); computes all 64 batches x 32 units
// (units [half*32, half*32+32)). W rows disjoint between halves (no DRAM
// refetch); x double-read is served from L2. Warp w: batches [w*16, w*16+16).
__global__ void __launch_bounds__(128, 6)
freeconv_mma_kernel(const float* __restrict__ x, const float* __restrict__ w,
                    const float* __restrict__ bias, float* __restrict__ out) {
    __shared__ float As[2][64][LDSS];
    __shared__ float Bs[2][32][LDSS];
    __shared__ float bsh[32];

    const int tid  = threadIdx.x;
    const int wid  = tid >> 5;
    const int lane = tid & 31;
    const int g    = lane >> 2;     // 0..7
    const int t    = lane & 3;      // 0..3
    const int tile = blockIdx.x >> 1;
    const int half = blockIdx.x & 1;
    const int oh = tile / OWw, ow = tile % OWw;
    const int ih0 = oh * 2, iw0 = ow * 2;

    uint64_t pol;
    asm("createpolicy.fractional.L2::evict_first.b64 %0, 1.0;" : "=l"(pol));

    if (tid < 32) bsh[tid] = bias[(size_t)tile * Uu + half * 32 + tid];

    // this half's 32 unit rows of W
    const size_t wtile = ((size_t)tile * Uu + half * 32) * KDIM;

    // Stage one K=32 chunk: A = 64 batch rows, B = 32 unit rows, 128B/row.
    auto load_chunk = [&](int c, int s) {
        const int ij = c >> 1, ch = c & 1;
        const int i = ij / 5, j = ij - i * 5;
        const float* xsrc = x + (((size_t)(ih0 + i) * Ww) + (iw0 + j)) * Cc + ch * 32;
        const float* wsrc = w + wtile + (size_t)c * 32;
        // B first: give the DRAM-bound W stream lead time
#pragma unroll
        for (int it = 0; it < 2; it++) {
            const int idx = tid + it * 128;      // 0..255
            const int row = idx >> 3, c16 = idx & 7;
            uint32_t bd = (uint32_t)__cvta_generic_to_shared(&Bs[s][row][0]) + c16 * 16;
            cp16_ef(bd, wsrc + (size_t)row * KDIM + c16 * 4, pol);
        }
#pragma unroll
        for (int it = 0; it < 4; it++) {
            const int idx = tid + it * 128;      // 0..511
            const int row = idx >> 3, c16 = idx & 7;
            uint32_t ad = (uint32_t)__cvta_generic_to_shared(&As[s][row][0]) + c16 * 16;
            cp16(ad, xsrc + (size_t)row * (Hh * Ww * Cc) + c16 * 4);
        }
    };

    float acc[4][4];
#pragma unroll
    for (int nt = 0; nt < 4; nt++)
#pragma unroll
        for (int r = 0; r < 4; r++) acc[nt][r] = 0.0f;

    load_chunk(0, 0);
    CP_COMMIT();

    const int warpM = wid * 16;   // warp's batch-row base

    for (int c = 0; c < NCHUNK; c++) {
        const int s = c & 1;
        if (c + 1 < NCHUNK) {
            load_chunk(c + 1, s ^ 1);
            CP_COMMIT();
            asm volatile("cp.async.wait_group 1;" ::: "memory");
        } else {
            asm volatile("cp.async.wait_group 0;" ::: "memory");
        }
        __syncthreads();

#pragma unroll
        for (int k8 = 0; k8 < 4; k8++) {
            const int kb = k8 * 8;
            uint32_t a[4], b[4][2];
            {
                const int r0 = warpM + g;
                a[0] = tf32_bits(As[s][r0][kb + t]);
                a[1] = tf32_bits(As[s][r0 + 8][kb + t]);
                a[2] = tf32_bits(As[s][r0][kb + t + 4]);
                a[3] = tf32_bits(As[s][r0 + 8][kb + t + 4]);
            }
#pragma unroll
            for (int nt = 0; nt < 4; nt++) {
                const int n0 = nt * 8 + g;
                b[nt][0] = tf32_bits(Bs[s][n0][kb + t]);
                b[nt][1] = tf32_bits(Bs[s][n0][kb + t + 4]);
            }
#pragma unroll
            for (int nt = 0; nt < 4; nt++)
                mma_16n8k8(acc[nt], a, b[nt]);
        }
        __syncthreads();
    }

    // epilogue: rows m = warpM+g (+8), cols u = half*32 + nt*8 + 2t
    const int r0 = warpM + g;
#pragma unroll
    for (int nt = 0; nt < 4; nt++) {
        const int col = nt * 8 + 2 * t;
        const float b0 = bsh[col], b1 = bsh[col + 1];
        const int gcol = half * 32 + col;
        float* op0 = out + (((size_t)r0 * OHh + oh) * OWw + ow) * Uu + gcol;
        float* op1 = out + (((size_t)(r0 + 8) * OHh + oh) * OWw + ow) * Uu + gcol;
        float2 v0 = make_float2(acc[nt][0] + b0, acc[nt][1] + b1);
        float2 v1 = make_float2(acc[nt][2] + b0, acc[nt][3] + b1);
        *reinterpret_cast<float2*>(op0) = v0;
        *reinterpret_cast<float2*>(op1) = v1;
    }
}

// ---------------- launch ----------------
extern "C" void kernel_launch(void* const* d_in, const int* in_sizes, int n_in,
                              void* d_out, int out_size) {
    (void)in_sizes; (void)n_in; (void)out_size;
    const float* x = (const float*)d_in[0];
    const float* w = (const float*)d_in[1];
    const float* b = (const float*)d_in[2];
    freeconv_mma_kernel<<<OHh * OWw * 2, 128>>>(x, w, b, (float*)d_out);
}

// round 13
// speedup vs baseline: 1.6355x; 1.3037x over previous
#include <cuda_runtime.h>
#include <cstdint>

// ---------------- problem constants ----------------
#define Hh  64
#define Ww  64
#define Cc  64
#define Uu  64
#define OHh 30
#define OWw 30
#define KDIM   1600           // 5*5*64
#define NCHUNK 50             // KDIM / 32
#define LDSS   36             // smem row stride in floats; LDS.128 conflict-free (see proof)

// Raw fp32 bits into the tf32 mma (truncation-to-tf32): no cvt in mainloop.
__device__ __forceinline__ uint32_t tf32_bits(float v) { return __float_as_uint(v); }

__device__ __forceinline__ void mma_16n8k8(float c[4], const uint32_t a[4], const uint32_t b[2]) {
    asm volatile(
        "mma.sync.aligned.m16n8k8.row.col.f32.tf32.tf32.f32 "
        "{%0,%1,%2,%3}, {%4,%5,%6,%7}, {%8,%9}, {%0,%1,%2,%3};"
        : "+f"(c[0]), "+f"(c[1]), "+f"(c[2]), "+f"(c[3])
        : "r"(a[0]), "r"(a[1]), "r"(a[2]), "r"(a[3]), "r"(b[0]), "r"(b[1]));
}

__device__ __forceinline__ void cp16(uint32_t dst, const float* src) {
    asm volatile("cp.async.cg.shared.global [%0], [%1], 16;" :: "r"(dst), "l"(src));
}
// W is streaming / read-once: evict_first so it doesn't blow x out of L2.
__device__ __forceinline__ void cp16_ef(uint32_t dst, const float* src, uint64_t pol) {
    asm volatile("cp.async.cg.shared.global.L2::cache_hint [%0], [%1], 16, %2;"
                 :: "r"(dst), "l"(src), "l"(pol));
}
#define CP_COMMIT() asm volatile("cp.async.commit_group;" ::: "memory")

// ---------------- kernel ----------------
// K-permutation: logical MMA slot (k8, lane t, half h) reads PHYSICAL col
// 8t + 2*k8 + h. A and B use the same map, so the GEMM is unchanged up to
// fp32 accumulation grouping. Each thread's (k8 in {2q,2q+1}) fragment data
// is one float4 at col 8t+4q -> LDS.128 instead of 4x LDS.32.
__global__ void __launch_bounds__(128, 6)
freeconv_mma_kernel(const float* __restrict__ x, const float* __restrict__ w,
                    const float* __restrict__ bias, float* __restrict__ out) {
    __shared__ float As[2][64][LDSS];
    __shared__ float Bs[2][64][LDSS];
    __shared__ float bsh[64];

    const int tid  = threadIdx.x;
    const int wid  = tid >> 5;
    const int lane = tid & 31;
    const int g    = lane >> 2;     // 0..7
    const int t    = lane & 3;      // 0..3
    const int tile = blockIdx.x;
    const int oh = tile / OWw, ow = tile % OWw;
    const int ih0 = oh * 2, iw0 = ow * 2;
    const int warpM = (wid >> 1) * 32;   // 0 or 32
    const int warpN = (wid & 1) * 32;    // 0 or 32

    uint64_t pol;
    asm("createpolicy.fractional.L2::evict_first.b64 %0, 1.0;" : "=l"(pol));

    if (tid < 64) bsh[tid] = bias[(size_t)tile * Uu + tid];

    const size_t wtile = (size_t)tile * Uu * KDIM;

    // Stage one K=32 chunk: A rows = 64 batches, B rows = 64 units, 128B/row.
    auto load_chunk = [&](int chunk, int s) {
        const int ij = chunk >> 1, ch = chunk & 1;
        const int i = ij / 5, j = ij - i * 5;
        const float* xsrc = x + (((size_t)(ih0 + i) * Ww) + (iw0 + j)) * Cc + ch * 32;
        const float* wsrc = w + wtile + (size_t)chunk * 32;
#pragma unroll
        for (int it = 0; it < 4; it++) {
            const int idx = tid + it * 128;      // 0..511
            const int row = idx >> 3, c16 = idx & 7;
            uint32_t ad = (uint32_t)__cvta_generic_to_shared(&As[s][row][0]) + c16 * 16;
            cp16(ad, xsrc + (size_t)row * (Hh * Ww * Cc) + c16 * 4);
            uint32_t bd = (uint32_t)__cvta_generic_to_shared(&Bs[s][row][0]) + c16 * 16;
            cp16_ef(bd, wsrc + (size_t)row * KDIM + c16 * 4, pol);
        }
    };

    float acc[2][4][4];
#pragma unroll
    for (int mt = 0; mt < 2; mt++)
#pragma unroll
        for (int nt = 0; nt < 4; nt++)
#pragma unroll
            for (int r = 0; r < 4; r++) acc[mt][nt][r] = 0.0f;

    load_chunk(0, 0);
    CP_COMMIT();

    const int fcol = 8 * t;   // this thread's fragment column base

    for (int c = 0; c < NCHUNK; c++) {
        const int s = c & 1;
        if (c + 1 < NCHUNK) {
            load_chunk(c + 1, s ^ 1);
            CP_COMMIT();
            asm volatile("cp.async.wait_group 1;" ::: "memory");
        } else {
            asm volatile("cp.async.wait_group 0;" ::: "memory");
        }
        __syncthreads();

#pragma unroll
        for (int q = 0; q < 2; q++) {            // half-pass: k8 = 2q, 2q+1
            const int co = fcol + 4 * q;
            float4 A4[2][2], B4[4];
#pragma unroll
            for (int mt = 0; mt < 2; mt++) {
                const int r0 = warpM + mt * 16 + g;
                A4[mt][0] = *reinterpret_cast<const float4*>(&As[s][r0][co]);
                A4[mt][1] = *reinterpret_cast<const float4*>(&As[s][r0 + 8][co]);
            }
#pragma unroll
            for (int nt = 0; nt < 4; nt++) {
                const int n0 = warpN + nt * 8 + g;
                B4[nt] = *reinterpret_cast<const float4*>(&Bs[s][n0][co]);
            }
#pragma unroll
            for (int k2 = 0; k2 < 2; k2++) {     // within half: element pair 2k2, 2k2+1
                uint32_t a[2][4], b[4][2];
#pragma unroll
                for (int mt = 0; mt < 2; mt++) {
                    const float* lo = reinterpret_cast<const float*>(&A4[mt][0]);
                    const float* hi = reinterpret_cast<const float*>(&A4[mt][1]);
                    a[mt][0] = tf32_bits(lo[2 * k2]);
                    a[mt][2] = tf32_bits(lo[2 * k2 + 1]);
                    a[mt][1] = tf32_bits(hi[2 * k2]);
                    a[mt][3] = tf32_bits(hi[2 * k2 + 1]);
                }
#pragma unroll
                for (int nt = 0; nt < 4; nt++) {
                    const float* bv = reinterpret_cast<const float*>(&B4[nt]);
                    b[nt][0] = tf32_bits(bv[2 * k2]);
                    b[nt][1] = tf32_bits(bv[2 * k2 + 1]);
                }
#pragma unroll
                for (int mt = 0; mt < 2; mt++)
#pragma unroll
                    for (int nt = 0; nt < 4; nt++)
                        mma_16n8k8(acc[mt][nt], a[mt], b[nt]);
            }
        }
        __syncthreads();
    }

    // epilogue: D[row=m, col=u] += bias[u]; out[b][oh][ow][u]
#pragma unroll
    for (int mt = 0; mt < 2; mt++) {
        const int r0 = warpM + mt * 16 + g;
#pragma unroll
        for (int nt = 0; nt < 4; nt++) {
            const int col = warpN + nt * 8 + 2 * t;
            const float b0 = bsh[col], b1 = bsh[col + 1];
            float* op0 = out + (((size_t)r0 * OHh + oh) * OWw + ow) * Uu + col;
            float* op1 = out + (((size_t)(r0 + 8) * OHh + oh) * OWw + ow) * Uu + col;
            float2 v0 = make_float2(acc[mt][nt][0] + b0, acc[mt][nt][1] + b1);
            float2 v1 = make_float2(acc[mt][nt][2] + b0, acc[mt][nt][3] + b1);
            *reinterpret_cast<float2*>(op0) = v0;
            *reinterpret_cast<float2*>(op1) = v1;
        }
    }
}

// ---------------- launch ----------------
extern "C" void kernel_launch(void* const* d_in, const int* in_sizes, int n_in,
                              void* d_out, int out_size) {
    (void)in_sizes; (void)n_in; (void)out_size;
    const float* x = (const float*)d_in[0];
    const float* w = (const float*)d_in[1];
    const float* b = (const float*)d_in[2];
    freeconv_mma_kernel<<<OHh * OWw, 128>>>(x, w, b, (float*)d_out);
}

// round 14
// speedup vs baseline: 1.6879x; 1.0320x over previous
#include <cuda_runtime.h>
#include <cstdint>

// ---------------- problem constants ----------------
#define Hh  64
#define Ww  64
#define Cc  64
#define Uu  64
#define OHh 30
#define OWw 30
#define KDIM   1600           // 5*5*64
#define NCHUNK 50             // KDIM / 32 (even)
#define LDSS   36             // smem row stride in floats (bank=(4g+t)%32 -> conflict-free)

// Raw fp32 bits into the tf32 mma (truncation-to-tf32): no cvt in mainloop.
__device__ __forceinline__ uint32_t tf32_bits(float v) { return __float_as_uint(v); }

__device__ __forceinline__ void mma_16n8k8(float c[4], const uint32_t a[4], const uint32_t b[2]) {
    asm volatile(
        "mma.sync.aligned.m16n8k8.row.col.f32.tf32.tf32.f32 "
        "{%0,%1,%2,%3}, {%4,%5,%6,%7}, {%8,%9}, {%0,%1,%2,%3};"
        : "+f"(c[0]), "+f"(c[1]), "+f"(c[2]), "+f"(c[3])
        : "r"(a[0]), "r"(a[1]), "r"(a[2]), "r"(a[3]), "r"(b[0]), "r"(b[1]));
}

__device__ __forceinline__ void cp16(uint32_t dst, const float* src) {
    asm volatile("cp.async.cg.shared.global [%0], [%1], 16;" :: "r"(dst), "l"(src));
}
// W is streaming / read-once: evict_first so it doesn't blow x out of L2.
__device__ __forceinline__ void cp16_ef(uint32_t dst, const float* src, uint64_t pol) {
    asm volatile("cp.async.cg.shared.global.L2::cache_hint [%0], [%1], 16, %2;"
                 :: "r"(dst), "l"(src), "l"(pol));
}
#define CP_COMMIT() asm volatile("cp.async.commit_group;" ::: "memory")
#define CP_WAIT0()  asm volatile("cp.async.wait_group 0;" ::: "memory")
#define CP_WAIT1()  asm volatile("cp.async.wait_group 1;" ::: "memory")

// ---------------- kernel ----------------
__global__ void __launch_bounds__(128, 6)
freeconv_mma_kernel(const float* __restrict__ x, const float* __restrict__ w,
                    const float* __restrict__ bias, float* __restrict__ out) {
    __shared__ float As[2][64][LDSS];
    __shared__ float Bs[2][64][LDSS];
    __shared__ float bsh[64];

    const int tid  = threadIdx.x;
    const int wid  = tid >> 5;
    const int lane = tid & 31;
    const int g    = lane >> 2;     // 0..7
    const int t    = lane & 3;      // 0..3
    const int tile = blockIdx.x;
    const int oh = tile / OWw, ow = tile % OWw;
    const int ih0 = oh * 2, iw0 = ow * 2;
    const int warpM = (wid >> 1) * 32;   // 0 or 32
    const int warpN = (wid & 1) * 32;    // 0 or 32

    uint64_t pol;
    asm("createpolicy.fractional.L2::evict_first.b64 %0, 1.0;" : "=l"(pol));

    if (tid < 64) bsh[tid] = bias[(size_t)tile * Uu + tid];

    const size_t wtile = (size_t)tile * Uu * KDIM;

    // Stage one K=32 chunk. B (W, DRAM ~600cyc) issued FIRST for head start;
    // A (x, L2-hit ~240cyc) after. wait_group unblocks on last completion.
    auto load_chunk = [&](int chunk, int s) {
        const int ij = chunk >> 1, ch = chunk & 1;
        const int i = ij / 5, j = ij - i * 5;
        const float* xsrc = x + (((size_t)(ih0 + i) * Ww) + (iw0 + j)) * Cc + ch * 32;
        const float* wsrc = w + wtile + (size_t)chunk * 32;
#pragma unroll
        for (int it = 0; it < 4; it++) {
            const int idx = tid + it * 128;      // 0..511
            const int row = idx >> 3, c16 = idx & 7;
            uint32_t bd = (uint32_t)__cvta_generic_to_shared(&Bs[s][row][0]) + c16 * 16;
            cp16_ef(bd, wsrc + (size_t)row * KDIM + c16 * 4, pol);
        }
#pragma unroll
        for (int it = 0; it < 4; it++) {
            const int idx = tid + it * 128;
            const int row = idx >> 3, c16 = idx & 7;
            uint32_t ad = (uint32_t)__cvta_generic_to_shared(&As[s][row][0]) + c16 * 16;
            cp16(ad, xsrc + (size_t)row * (Hh * Ww * Cc) + c16 * 4);
        }
    };

    float acc[2][4][4];
#pragma unroll
    for (int mt = 0; mt < 2; mt++)
#pragma unroll
        for (int nt = 0; nt < 4; nt++)
#pragma unroll
            for (int r = 0; r < 4; r++) acc[mt][nt][r] = 0.0f;

    // compute chunk resident in stage S (compile-time constant)
    auto compute = [&](const int S) {
#pragma unroll
        for (int k8 = 0; k8 < 4; k8++) {
            const int kb = k8 * 8;
            uint32_t a[2][4], b[4][2];
#pragma unroll
            for (int mt = 0; mt < 2; mt++) {
                const int r0 = warpM + mt * 16 + g;
                a[mt][0] = tf32_bits(As[S][r0][kb + t]);
                a[mt][1] = tf32_bits(As[S][r0 + 8][kb + t]);
                a[mt][2] = tf32_bits(As[S][r0][kb + t + 4]);
                a[mt][3] = tf32_bits(As[S][r0 + 8][kb + t + 4]);
            }
#pragma unroll
            for (int nt = 0; nt < 4; nt++) {
                const int n0 = warpN + nt * 8 + g;
                b[nt][0] = tf32_bits(Bs[S][n0][kb + t]);
                b[nt][1] = tf32_bits(Bs[S][n0][kb + t + 4]);
            }
#pragma unroll
            for (int mt = 0; mt < 2; mt++)
#pragma unroll
                for (int nt = 0; nt < 4; nt++)
                    mma_16n8k8(acc[mt][nt], a[mt], b[nt]);
        }
    };

    load_chunk(0, 0);
    CP_COMMIT();

    // R6 ordering exactly, unrolled x2 so stage indices are literals.
    // Per chunk c: [load c+1 -> commit -> wait1] -> sync -> compute(c) -> sync
    for (int d = 0; d < NCHUNK / 2; d++) {
        const int c0 = 2 * d;

        // chunk c0 (stage 0); c0+1 <= 49 always exists
        load_chunk(c0 + 1, 1);
        CP_COMMIT();
        CP_WAIT1();
        __syncthreads();
        compute(0);
        __syncthreads();

        // chunk c0+1 (stage 1)
        if (c0 + 2 < NCHUNK) {
            load_chunk(c0 + 2, 0);
            CP_COMMIT();
            CP_WAIT1();
        } else {
            CP_WAIT0();
        }
        __syncthreads();
        compute(1);
        __syncthreads();
    }

    // epilogue: D[row=m, col=u] += bias[u]; out[b][oh][ow][u]
#pragma unroll
    for (int mt = 0; mt < 2; mt++) {
        const int r0 = warpM + mt * 16 + g;
#pragma unroll
        for (int nt = 0; nt < 4; nt++) {
            const int col = warpN + nt * 8 + 2 * t;
            const float b0 = bsh[col], b1 = bsh[col + 1];
            float* op0 = out + (((size_t)r0 * OHh + oh) * OWw + ow) * Uu + col;
            float* op1 = out + (((size_t)(r0 + 8) * OHh + oh) * OWw + ow) * Uu + col;
            float2 v0 = make_float2(acc[mt][nt][0] + b0, acc[mt][nt][1] + b1);
            float2 v1 = make_float2(acc[mt][nt][2] + b0, acc[mt][nt][3] + b1);
            *reinterpret_cast<float2*>(op0) = v0;
            *reinterpret_cast<float2*>(op1) = v1;
        }
    }
}

// ---------------- launch ----------------
extern "C" void kernel_launch(void* const* d_in, const int* in_sizes, int n_in,
                              void* d_out, int out_size) {
    (void)in_sizes; (void)n_in; (void)out_size;
    const float* x = (const float*)d_in[0];
    const float* w = (const float*)d_in[1];
    const float* b = (const float*)d_in[2];
    freeconv_mma_kernel<<<OHh * OWw, 128>>>(x, w, b, (float*)d_out);
}